// round 15
// baseline (speedup 1.0000x reference)
#include <cuda_runtime.h>
#include <cuda_fp16.h>
#include <math.h>
#include <stdint.h>

#define BATCH 8
#define NTOK  1024
#define DMODEL 512
#define HEADS 8
#define DHEAD 64
#define CHh 6
#define CDd 64
#define IDIM 512
#define TOKENS (BATCH*NTOK)   // 8192
#define CKDIM (CHh*CDd)       // 384

typedef __half f16;

// ---------------- weight split offsets (elements) ------------------------------
#define OFF_WQKV 0
#define OFF_CKW0 786432
#define OFF_CKW1 983040
#define OFF_CKW2 1245184
#define OFF_CVW0 1507328
#define OFF_CVW1 1703936
#define OFF_CVW2 1966080
#define OFF_NLW  2228224
#define OFF_WOUT 2490368
#define W_TOTAL  2752512
#define X_ELEMS  (TOKENS * DMODEL)
#define ALL_SPLIT (W_TOTAL + X_ELEMS)

// ---------------- scratch ----------------------------------------------------
__device__ f16 g_wh[W_TOTAL];                 // weights: hi only
__device__ f16 g_xh[X_ELEMS], g_xl[X_ELEMS];
__device__ f16 g_qkvh[TOKENS * 3 * IDIM];     // qkv: hi only
__device__ f16 g_ckxh[TOKENS * CKDIM],    g_ckxl[TOKENS * CKDIM];
__device__ f16 g_cvxh[TOKENS * CKDIM],    g_cvxl[TOKENS * CKDIM];
__device__ f16 g_tah [TOKENS * IDIM],     g_tal [TOKENS * IDIM];
__device__ f16 g_tbh [TOKENS * IDIM],     g_tbl [TOKENS * IDIM];
__device__ f16 g_uah [TOKENS * IDIM],     g_ual [TOKENS * IDIM];
__device__ f16 g_ubh [TOKENS * IDIM],     g_ubl [TOKENS * IDIM];
__device__ f16 g_ckhh[TOKENS * IDIM];         // K ctx: hi only
__device__ f16 g_cvhh[TOKENS * IDIM];         // V ctx: hi only
__device__ f16 g_cmh [TOKENS * IDIM],     g_cml [TOKENS * IDIM];
__device__ float g_oself[TOKENS * IDIM];
__device__ float g_octx [TOKENS * IDIM];

// ---------------- helpers ----------------------------------------------------
__device__ __forceinline__ void mma_f16(float c[4],
    uint32_t a0, uint32_t a1, uint32_t a2, uint32_t a3,
    uint32_t b0, uint32_t b1)
{
    asm volatile(
        "mma.sync.aligned.m16n8k16.row.col.f32.f16.f16.f32 "
        "{%0,%1,%2,%3}, {%4,%5,%6,%7}, {%8,%9}, {%0,%1,%2,%3};\n"
        : "+f"(c[0]), "+f"(c[1]), "+f"(c[2]), "+f"(c[3])
        : "r"(a0), "r"(a1), "r"(a2), "r"(a3), "r"(b0), "r"(b1));
}
__device__ __forceinline__ void ldsm4(uint32_t& r0, uint32_t& r1, uint32_t& r2, uint32_t& r3,
                                      const void* p)
{
    uint32_t a = (uint32_t)__cvta_generic_to_shared(p);
    asm volatile("ldmatrix.sync.aligned.m8n8.x4.shared.b16 {%0,%1,%2,%3}, [%4];"
        : "=r"(r0), "=r"(r1), "=r"(r2), "=r"(r3) : "r"(a));
}
__device__ __forceinline__ void ldsm4t(uint32_t& r0, uint32_t& r1, uint32_t& r2, uint32_t& r3,
                                       const void* p)
{
    uint32_t a = (uint32_t)__cvta_generic_to_shared(p);
    asm volatile("ldmatrix.sync.aligned.m8n8.x4.trans.shared.b16 {%0,%1,%2,%3}, [%4];"
        : "=r"(r0), "=r"(r1), "=r"(r2), "=r"(r3) : "r"(a));
}
__device__ __forceinline__ void cp16(void* dst, const void* src) {
    uint32_t d = (uint32_t)__cvta_generic_to_shared(dst);
    asm volatile("cp.async.cg.shared.global [%0], [%1], 16;" :: "r"(d), "l"(src));
}
__device__ __forceinline__ uint32_t packh(float x, float y) {
    __half2 t = __floats2half2_rn(x, y);
    return *(uint32_t*)&t;
}
__device__ __forceinline__ void hilo(float x, float& h, float& l) {
    f16 hb = __float2half_rn(x);
    h = __half2float(hb);
    l = x - h;
}

// ---------------- prep: weight/x split + ck/cv colnorm in ONE launch ------------
// z = 0: split (grid.x covers ALL_SPLIT/4/512 blocks of 512 threads)
// z = 1: colnorm (grid.x < CHh*BATCH*2 -> decode)
struct WSrcs { const float* p[10]; };

__global__ __launch_bounds__(512) void prep_all(WSrcs w,
    const float* __restrict__ ck, const float* __restrict__ cv)
{
    if (blockIdx.z == 0) {
        const int offs[11] = {OFF_WQKV, OFF_CKW0, OFF_CKW1, OFF_CKW2, OFF_CVW0,
                              OFF_CVW1, OFF_CVW2, OFF_NLW, OFF_WOUT, W_TOTAL, ALL_SPLIT};
        int idx = (blockIdx.x * 512 + threadIdx.x) * 4;
        if (idx >= ALL_SPLIT) return;
        int seg = 0;
        while (idx >= offs[seg + 1]) seg++;
        float4 v = *(const float4*)(w.p[seg] + (idx - offs[seg]));
        float h0,l0,h1,l1,h2,l2,h3,l3;
        hilo(v.x,h0,l0); hilo(v.y,h1,l1); hilo(v.z,h2,l2); hilo(v.w,h3,l3);
        if (seg < 9) {
            *(uint32_t*)&g_wh[idx]     = packh(h0,h1);
            *(uint32_t*)&g_wh[idx + 2] = packh(h2,h3);
        } else {
            int di = idx - W_TOTAL;
            *(uint32_t*)&g_xh[di]     = packh(h0,h1);
            *(uint32_t*)&g_xh[di + 2] = packh(h2,h3);
            *(uint32_t*)&g_xl[di]     = packh(l0,l1);
            *(uint32_t*)&g_xl[di + 2] = packh(l2,l3);
        }
        return;
    }
    // z == 1: colnorm over ck/cv.  blockIdx.x in [0, CHh*BATCH*2)
    int t = blockIdx.x;
    if (t >= CHh * BATCH * 2) return;
    const int zz = t / (CHh * BATCH);
    t %= CHh * BATCH;
    const int b = t / CHh, hh = t % CHh;
    const float* src = zz ? cv : ck;
    f16* dh = zz ? g_cvxh : g_ckxh;
    f16* dl = zz ? g_cvxl : g_ckxl;
    __shared__ float red[512];
    __shared__ float inv[64];
    const int tid = threadIdx.x;
    const int d = tid & 63;
    const int ng = tid >> 6;
    const float* s = src + (((size_t)b * CHh + hh) * NTOK) * CDd;
    float acc = 0.0f;
    for (int n = ng; n < NTOK; n += 8) {
        float v = s[(size_t)n * CDd + d];
        acc += v * v;
    }
    red[tid] = acc;
    __syncthreads();
    if (tid < 64) {
        float tt = 0.0f;
#pragma unroll
        for (int i = 0; i < 8; i++) tt += red[tid + i * 64];
        inv[tid] = 1.0f / fmaxf(sqrtf(tt), 1e-12f);
    }
    __syncthreads();
    float iv = inv[d];
    f16* ph = dh + (size_t)b * NTOK * CKDIM + hh * CDd;
    f16* pl = dl + (size_t)b * NTOK * CKDIM + hh * CDd;
    for (int n = ng; n < NTOK; n += 8) {
        float v = s[(size_t)n * CDd + d] * iv;
        float h, l;
        hilo(v, h, l);
        ph[(size_t)n * CKDIM + d] = __float2half_rn(h);
        pl[(size_t)n * CKDIM + d] = __float2half_rn(l);
    }
}

// ---------------- fp16 2-product GEMM, BK=64, 3-stage cp.async -----------------
// Linear-grid variant: each z-config has ntile = (N/128)*(M/128) tiles; block
// linear id decodes (z, bx, by) with NO dead blocks.
#define SLD 72
#define AST (128 * SLD)
#define STAGE_E (3 * AST)              // Ah|Al|Bh
#define GEMM_SMEM (3 * STAGE_E * 2)    // 165888 bytes

struct GArg {
    const f16 *Ah, *Al, *Bh;
    const float* bias;
    float* Cf;
    f16 *Ch, *Cl;
    const float* ratio;
    int N, K, act, aout, tile0;   // tile0 = first linear tile id of this config
};
struct GArg3 { GArg a[3]; };

__global__ __launch_bounds__(512) void gemm_u(GArg3 args, int nz)
{
    extern __shared__ __align__(16) f16 smg[];
    // decode linear tile id -> (z, bx, by)
    int t = blockIdx.x;
    int z = nz - 1;
#pragma unroll
    for (int i = 1; i < 3; i++)
        if (i < nz && t < args.a[i].tile0) { z = i - 1; break; }
    const GArg g = args.a[z];
    t -= g.tile0;
    const int nbx = g.N / 128;
    const int bx = t % nbx, by = t / nbx;
    const int N = g.N, K = g.K;
    const int tid = threadIdx.x, lane = tid & 31, warp = tid >> 5;
    const int lr = lane >> 2, lc = lane & 3;
    const int wm = warp >> 2, wn = warp & 3;

    const f16* AhB = g.Ah + (size_t)by * 128 * K;
    const f16* AlB = g.Al + (size_t)by * 128 * K;
    const f16* BhB = g.Bh + (size_t)bx * 128 * K;

    int lrow[2], lcg[2];
#pragma unroll
    for (int i = 0; i < 2; i++) {
        int f = tid + i * 512;
        lrow[i] = f >> 3;
        lcg[i] = (f & 7) * 8;
    }
    const int a_r = wm * 32 + (lane & 15);
    const int a_c0 = (lane >> 4) * 8;
    const int b_r = wn * 32 + (lane & 7) + ((lane & 16) ? 8 : 0);
    const int b_c0 = (lane & 8) ? 8 : 0;

    float acc[2][4][4];
#pragma unroll
    for (int i = 0; i < 2; i++)
#pragma unroll
        for (int j = 0; j < 4; j++)
#pragma unroll
            for (int r = 0; r < 4; r++) acc[i][j][r] = 0.0f;

    const int ktiles = K / 64;

    auto issue = [&](int kt, int buf) {
        f16* s = smg + buf * STAGE_E;
        int kg = kt * 64;
#pragma unroll
        for (int i = 0; i < 2; i++) {
            size_t go = (size_t)lrow[i] * K + kg + lcg[i];
            int so = lrow[i] * SLD + lcg[i];
            cp16(s + so,            AhB + go);
            cp16(s + AST + so,      AlB + go);
            cp16(s + 2 * AST + so,  BhB + go);
        }
        asm volatile("cp.async.commit_group;");
    };
    issue(0, 0);
    if (ktiles > 1) issue(1, 1);

    for (int kt = 0; kt < ktiles; kt++) {
        if (kt < ktiles - 1) asm volatile("cp.async.wait_group 1;");
        else                 asm volatile("cp.async.wait_group 0;");
        __syncthreads();
        if (kt + 2 < ktiles) issue(kt + 2, (kt + 2) % 3);

        const f16* s = smg + (kt % 3) * STAGE_E;
        const f16* AhS = s;
        const f16* AlS = s + AST;
        const f16* BhS = s + 2 * AST;
#pragma unroll
        for (int ks = 0; ks < 64; ks += 16) {
            uint32_t ah[2][4], al_[2][4], bh[4][2];
#pragma unroll
            for (int i = 0; i < 2; i++) {
                ldsm4(ah[i][0], ah[i][1], ah[i][2], ah[i][3],
                      AhS + (a_r + i * 16) * SLD + a_c0 + ks);
                ldsm4(al_[i][0], al_[i][1], al_[i][2], al_[i][3],
                      AlS + (a_r + i * 16) * SLD + a_c0 + ks);
            }
#pragma unroll
            for (int jp = 0; jp < 2; jp++) {
                ldsm4(bh[2*jp][0], bh[2*jp][1], bh[2*jp+1][0], bh[2*jp+1][1],
                      BhS + (b_r + jp * 16) * SLD + b_c0 + ks);
            }
#pragma unroll
            for (int i = 0; i < 2; i++)
#pragma unroll
                for (int j = 0; j < 4; j++)
                    mma_f16(acc[i][j], ah[i][0],ah[i][1],ah[i][2],ah[i][3], bh[j][0],bh[j][1]);
#pragma unroll
            for (int i = 0; i < 2; i++)
#pragma unroll
                for (int j = 0; j < 4; j++)
                    mma_f16(acc[i][j], al_[i][0],al_[i][1],al_[i][2],al_[i][3], bh[j][0],bh[j][1]);
        }
    }

    // epilogue (runtime act/aout)
#pragma unroll
    for (int i = 0; i < 2; i++) {
        int row0 = by * 128 + wm * 32 + i * 16 + lr;
#pragma unroll
        for (int j = 0; j < 4; j++) {
            int col = bx * 128 + wn * 32 + j * 8 + 2 * lc;
            float b0 = g.bias ? g.bias[col]     : 0.0f;
            float b1 = g.bias ? g.bias[col + 1] : 0.0f;
            float v[4];
            v[0] = acc[i][j][0] + b0; v[1] = acc[i][j][1] + b1;
            v[2] = acc[i][j][2] + b0; v[3] = acc[i][j][3] + b1;
#pragma unroll
            for (int r = 0; r < 4; r++) {
                float xx = v[r];
                if (g.act == 1) xx = xx > 0.0f ? xx : 0.2f * xx;
                else if (g.act == 2) xx = 0.5f * xx * (1.0f + erff(xx * 0.70710678118654752f));
                v[r] = xx;
            }
            if (g.aout == 0) {
                *(float2*)(g.Cf + (size_t)row0 * N + col)       = make_float2(v[0], v[1]);
                *(float2*)(g.Cf + (size_t)(row0 + 8) * N + col) = make_float2(v[2], v[3]);
            } else if (g.aout == 1) {
                float h0,l0,h1,l1;
                hilo(v[0],h0,l0); hilo(v[1],h1,l1);
                *(uint32_t*)&g.Ch[(size_t)row0 * N + col] = packh(h0,h1);
                *(uint32_t*)&g.Cl[(size_t)row0 * N + col] = packh(l0,l1);
                hilo(v[2],h0,l0); hilo(v[3],h1,l1);
                *(uint32_t*)&g.Ch[(size_t)(row0 + 8) * N + col] = packh(h0,h1);
                *(uint32_t*)&g.Cl[(size_t)(row0 + 8) * N + col] = packh(l0,l1);
            } else if (g.aout == 2) {
                float2 s0 = *(const float2*)(g.Cf + (size_t)row0 * N + col);
                float2 s1 = *(const float2*)(g.Cf + (size_t)(row0 + 8) * N + col);
                float2 rr = *(const float2*)(g.ratio + col);
                float c0 = s0.x - v[0] * rr.x, c1 = s0.y - v[1] * rr.y;
                float c2 = s1.x - v[2] * rr.x, c3 = s1.y - v[3] * rr.y;
                float h0,l0,h1,l1;
                hilo(c0,h0,l0); hilo(c1,h1,l1);
                *(uint32_t*)&g.Ch[(size_t)row0 * N + col] = packh(h0,h1);
                *(uint32_t*)&g.Cl[(size_t)row0 * N + col] = packh(l0,l1);
                hilo(c2,h0,l0); hilo(c3,h1,l1);
                *(uint32_t*)&g.Ch[(size_t)(row0 + 8) * N + col] = packh(h0,h1);
                *(uint32_t*)&g.Cl[(size_t)(row0 + 8) * N + col] = packh(l0,l1);
            } else {  // aout == 3: hi only
                *(uint32_t*)&g.Ch[(size_t)row0 * N + col]       = packh(v[0], v[1]);
                *(uint32_t*)&g.Ch[(size_t)(row0 + 8) * N + col] = packh(v[2], v[3]);
            }
        }
    }
}

// ---------------- fp16 fixed-base flash attention (double-buffered smem) --------
#define KLD 72

struct AArg {
    const f16 *Kh, *Vh;
    float* O;
    int ldkv;
};
struct AArg2 { AArg a[2]; };

__global__ __launch_bounds__(256) void attn_mma(
    const f16* __restrict__ Qh, AArg2 args, int ldq)
{
    __shared__ f16 Kh[2][64][KLD];
    __shared__ f16 Vh[2][64][KLD];
    const int b = blockIdx.z & 7, br = blockIdx.z >> 3;
    const int h = blockIdx.y, qt = blockIdx.x;
    const AArg ar = args.a[br];
    const int ldkv = ar.ldkv;
    const int tid = threadIdx.x;
    const int lane = tid & 31, warp = tid >> 5;
    const int lr = lane >> 2, lc = lane & 3;

    const f16* QhB = Qh + ((size_t)b * NTOK + qt * 128 + warp * 16) * ldq + h * 64;
    const f16* KhB = ar.Kh + ((size_t)b * NTOK) * ldkv + h * 64;
    const f16* VhB = ar.Vh + ((size_t)b * NTOK) * ldkv + h * 64;

    uint32_t qh[4][4];
#pragma unroll
    for (int kk = 0; kk < 4; kk++) {
        qh[kk][0] = *(const uint32_t*)&QhB[(size_t)lr * ldq + kk*16 + 2*lc];
        qh[kk][1] = *(const uint32_t*)&QhB[(size_t)(lr+8) * ldq + kk*16 + 2*lc];
        qh[kk][2] = *(const uint32_t*)&QhB[(size_t)lr * ldq + kk*16 + 8 + 2*lc];
        qh[kk][3] = *(const uint32_t*)&QhB[(size_t)(lr+8) * ldq + kk*16 + 8 + 2*lc];
    }

    int krow[2], kcg[2];
#pragma unroll
    for (int i = 0; i < 2; i++) {
        int f = tid + i * 256;
        krow[i] = f >> 3;
        kcg[i] = (f & 7) * 8;
    }
    const int k_r = (lane & 7) + ((lane & 16) ? 8 : 0);
    const int k_c = (lane & 8) ? 8 : 0;
    const int v_r = (lane & 7) + ((lane & 8) ? 8 : 0);
    const int v_c = (lane & 16) ? 8 : 0;

    float l0p = 0.0f, l1p = 0.0f;
    float o[8][4];
#pragma unroll
    for (int j = 0; j < 8; j++)
#pragma unroll
        for (int r = 0; r < 4; r++) o[j][r] = 0.0f;

    // preload tile 0 -> buffer 0
    uint4 pkh[2], pvh[2];
#pragma unroll
    for (int i = 0; i < 2; i++) {
        size_t off = (size_t)krow[i] * ldkv + kcg[i];
        pkh[i] = *(const uint4*)(KhB + off);
        pvh[i] = *(const uint4*)(VhB + off);
    }
#pragma unroll
    for (int i = 0; i < 2; i++) {
        *(uint4*)&Kh[0][krow[i]][kcg[i]] = pkh[i];
        *(uint4*)&Vh[0][krow[i]][kcg[i]] = pvh[i];
    }
    __syncthreads();

    const int T = NTOK / 64;
    for (int kt = 0; kt < T; kt++) {
        const int buf = kt & 1;

        // prefetch next tile into registers
        if (kt + 1 < T) {
            const f16* Kn = KhB + (size_t)(kt + 1) * 64 * ldkv;
            const f16* Vn = VhB + (size_t)(kt + 1) * 64 * ldkv;
#pragma unroll
            for (int i = 0; i < 2; i++) {
                size_t off = (size_t)krow[i] * ldkv + kcg[i];
                pkh[i] = *(const uint4*)(Kn + off);
                pvh[i] = *(const uint4*)(Vn + off);
            }
        }

        // S = Qh Kh^T
        float s[8][4];
#pragma unroll
        for (int j = 0; j < 8; j++)
#pragma unroll
            for (int r = 0; r < 4; r++) s[j][r] = 0.0f;
#pragma unroll
        for (int kk = 0; kk < 4; kk++) {
#pragma unroll
            for (int jp = 0; jp < 4; jp++) {
                uint32_t kb0,kb1,kb2,kb3;
                ldsm4(kb0,kb1,kb2,kb3, &Kh[buf][jp*16 + k_r][kk*16 + k_c]);
                mma_f16(s[2*jp],   qh[kk][0],qh[kk][1],qh[kk][2],qh[kk][3], kb0, kb1);
                mma_f16(s[2*jp+1], qh[kk][0],qh[kk][1],qh[kk][2],qh[kk][3], kb2, kb3);
            }
        }

        // P = exp(s * scale); partial row sums
#pragma unroll
        for (int j = 0; j < 8; j++) {
            s[j][0] = __expf(s[j][0] * 0.125f);
            s[j][1] = __expf(s[j][1] * 0.125f);
            s[j][2] = __expf(s[j][2] * 0.125f);
            s[j][3] = __expf(s[j][3] * 0.125f);
            l0p += s[j][0] + s[j][1];
            l1p += s[j][2] + s[j][3];
        }

        // O += P V
#pragma unroll
        for (int kk = 0; kk < 4; kk++) {
            uint32_t pah0 = packh(s[2*kk][0],   s[2*kk][1]);
            uint32_t pah1 = packh(s[2*kk][2],   s[2*kk][3]);
            uint32_t pah2 = packh(s[2*kk+1][0], s[2*kk+1][1]);
            uint32_t pah3 = packh(s[2*kk+1][2], s[2*kk+1][3]);
#pragma unroll
            for (int jp = 0; jp < 4; jp++) {
                uint32_t vb0,vb1,vb2,vb3;
                ldsm4t(vb0,vb1,vb2,vb3, &Vh[buf][kk*16 + v_r][jp*16 + v_c]);
                mma_f16(o[2*jp],   pah0,pah1,pah2,pah3, vb0, vb1);
                mma_f16(o[2*jp+1], pah0,pah1,pah2,pah3, vb2, vb3);
            }
        }

        // store prefetched tile into the other buffer, single sync
        if (kt + 1 < T) {
            const int nb = buf ^ 1;
#pragma unroll
            for (int i = 0; i < 2; i++) {
                *(uint4*)&Kh[nb][krow[i]][kcg[i]] = pkh[i];
                *(uint4*)&Vh[nb][krow[i]][kcg[i]] = pvh[i];
            }
            __syncthreads();
        }
    }

    l0p += __shfl_xor_sync(0xffffffffu, l0p, 1);
    l0p += __shfl_xor_sync(0xffffffffu, l0p, 2);
    l1p += __shfl_xor_sync(0xffffffffu, l1p, 1);
    l1p += __shfl_xor_sync(0xffffffffu, l1p, 2);
    float inv0 = 1.0f / l0p, inv1 = 1.0f / l1p;

    float* Op = ar.O + ((size_t)b * NTOK + qt * 128 + warp * 16) * IDIM + h * 64;
#pragma unroll
    for (int j = 0; j < 8; j++) {
        int col = j * 8 + 2 * lc;
        *(float2*)(Op + (size_t)lr * IDIM + col)       = make_float2(o[j][0]*inv0, o[j][1]*inv0);
        *(float2*)(Op + (size_t)(lr + 8) * IDIM + col) = make_float2(o[j][2]*inv1, o[j][3]*inv1);
    }
}

// ---------------- column L2-norm over tokens of octx (512 threads) --------------
__global__ __launch_bounds__(512) void colnorm_tok_kernel(
    const float* __restrict__ src, f16* __restrict__ dh, f16* __restrict__ dl)
{
    const int hh = blockIdx.x, b = blockIdx.y;
    __shared__ float red[512];
    __shared__ float inv[64];
    const int tid = threadIdx.x;
    const int d = tid & 63;
    const int ng = tid >> 6;
    const float* s = src + (size_t)b * NTOK * IDIM + hh * 64;
    float acc = 0.0f;
    for (int n = ng; n < NTOK; n += 8) {
        float v = s[(size_t)n * IDIM + d];
        acc += v * v;
    }
    red[tid] = acc;
    __syncthreads();
    if (tid < 64) {
        float t = 0.0f;
#pragma unroll
        for (int i = 0; i < 8; i++) t += red[tid + i * 64];
        inv[tid] = 1.0f / fmaxf(sqrtf(t), 1e-12f);
    }
    __syncthreads();
    float iv = inv[d];
    f16* ph = dh + (size_t)b * NTOK * IDIM + hh * 64;
    f16* pl = dl + (size_t)b * NTOK * IDIM + hh * 64;
    for (int n = ng; n < NTOK; n += 8) {
        float v = s[(size_t)n * IDIM + d] * iv;
        float h, l;
        hilo(v, h, l);
        ph[(size_t)n * IDIM + d] = __float2half_rn(h);
        pl[(size_t)n * IDIM + d] = __float2half_rn(l);
    }
}

// ---------------- launch -------------------------------------------------------
extern "C" void kernel_launch(void* const* d_in, const int* in_sizes, int n_in,
                              void* d_out, int out_size)
{
    const float* x      = (const float*)d_in[0];
    const float* ck     = (const float*)d_in[1];
    const float* cv     = (const float*)d_in[2];
    const float* b_out  = (const float*)d_in[5];
    const float* ckb0   = (const float*)d_in[7];
    const float* ckb1   = (const float*)d_in[9];
    const float* ckb2   = (const float*)d_in[11];
    const float* cvb0   = (const float*)d_in[13];
    const float* cvb1   = (const float*)d_in[15];
    const float* cvb2   = (const float*)d_in[17];
    const float* nl_b   = (const float*)d_in[19];
    const float* ratio  = (const float*)d_in[20];
    float* out = (float*)d_out;

    f16 *wh, *xh, *xl, *qkvh, *ckxh, *ckxl, *cvxh, *cvxl;
    f16 *tah, *tal, *tbh, *tbl, *uah, *ual, *ubh, *ubl;
    f16 *ckhh, *cvhh, *cmh, *cml;
    float *oself, *octx;
    cudaGetSymbolAddress((void**)&wh,   g_wh);
    cudaGetSymbolAddress((void**)&xh,   g_xh);
    cudaGetSymbolAddress((void**)&xl,   g_xl);
    cudaGetSymbolAddress((void**)&qkvh, g_qkvh);
    cudaGetSymbolAddress((void**)&ckxh, g_ckxh);
    cudaGetSymbolAddress((void**)&ckxl, g_ckxl);
    cudaGetSymbolAddress((void**)&cvxh, g_cvxh);
    cudaGetSymbolAddress((void**)&cvxl, g_cvxl);
    cudaGetSymbolAddress((void**)&tah,  g_tah);
    cudaGetSymbolAddress((void**)&tal,  g_tal);
    cudaGetSymbolAddress((void**)&tbh,  g_tbh);
    cudaGetSymbolAddress((void**)&tbl,  g_tbl);
    cudaGetSymbolAddress((void**)&uah,  g_uah);
    cudaGetSymbolAddress((void**)&ual,  g_ual);
    cudaGetSymbolAddress((void**)&ubh,  g_ubh);
    cudaGetSymbolAddress((void**)&ubl,  g_ubl);
    cudaGetSymbolAddress((void**)&ckhh, g_ckhh);
    cudaGetSymbolAddress((void**)&cvhh, g_cvhh);
    cudaGetSymbolAddress((void**)&cmh,  g_cmh);
    cudaGetSymbolAddress((void**)&cml,  g_cml);
    cudaGetSymbolAddress((void**)&oself,g_oself);
    cudaGetSymbolAddress((void**)&octx, g_octx);

    cudaFuncSetAttribute(gemm_u, cudaFuncAttributeMaxDynamicSharedMemorySize, GEMM_SMEM);

    // 0) prep: split weights/x + ck/cv colnorm in one launch
    WSrcs ws;
    ws.p[0] = (const float*)d_in[3];  // w_qkv
    ws.p[1] = (const float*)d_in[6];  // ckw0
    ws.p[2] = (const float*)d_in[8];  // ckw1
    ws.p[3] = (const float*)d_in[10]; // ckw2
    ws.p[4] = (const float*)d_in[12]; // cvw0
    ws.p[5] = (const float*)d_in[14]; // cvw1
    ws.p[6] = (const float*)d_in[16]; // cvw2
    ws.p[7] = (const float*)d_in[18]; // nl_w
    ws.p[8] = (const float*)d_in[4];  // w_out
    ws.p[9] = x;
    {
        int nsplit = (ALL_SPLIT / 4 + 511) / 512;   // 3360
        prep_all<<<dim3(nsplit, 1, 2), 512>>>(ws, ck, cv);
    }

    GArg3 ga;

    // 1) merged: qkv GEMM + vectorizer L0 ck + L0 cv (linear grid, 1280 tiles)
    ga.a[0] = {xh,   xl,   wh + OFF_WQKV, nullptr, nullptr, qkvh, nullptr, nullptr,
               3 * IDIM, DMODEL, 0, 3, 0};
    ga.a[1] = {ckxh, ckxl, wh + OFF_CKW0, ckb0,    nullptr, tah,  tal,  nullptr,
               IDIM, CKDIM, 1, 1, 768};
    ga.a[2] = {cvxh, cvxl, wh + OFF_CKW0 + (OFF_CVW0 - OFF_CKW0), cvb0, nullptr, uah, ual, nullptr,
               IDIM, CKDIM, 1, 1, 1024};
    gemm_u<<<1280, 512, GEMM_SMEM>>>(ga, 3);

    // 2) vectorizer L1 (ck/cv, linear grid, 512 tiles)
    ga.a[0] = {tah, tal, wh + OFF_CKW1, ckb1, nullptr, tbh, tbl, nullptr,
               IDIM, IDIM, 1, 1, 0};
    ga.a[1] = {uah, ual, wh + OFF_CVW1, cvb1, nullptr, ubh, ubl, nullptr,
               IDIM, IDIM, 1, 1, 256};
    gemm_u<<<512, 512, GEMM_SMEM>>>(ga, 2);

    // 3) vectorizer L2 (ck/cv, hi-only out)
    ga.a[0] = {tbh, tbl, wh + OFF_CKW2, ckb2, nullptr, ckhh, nullptr, nullptr,
               IDIM, IDIM, 1, 3, 0};
    ga.a[1] = {ubh, ubl, wh + OFF_CVW2, cvb2, nullptr, cvhh, nullptr, nullptr,
               IDIM, IDIM, 1, 3, 256};
    gemm_u<<<512, 512, GEMM_SMEM>>>(ga, 2);

    // 4) both attention branches in one launch
    AArg2 aa;
    aa.a[0] = {qkvh + IDIM, qkvh + 2 * IDIM, oself, 3 * IDIM};
    aa.a[1] = {ckhh, cvhh, octx, IDIM};
    attn_mma<<<dim3(NTOK / 128, HEADS, 2 * BATCH), 256>>>(qkvh, aa, 3 * IDIM);

    // 5) MLP colnorm
    colnorm_tok_kernel<<<dim3(IDIM / 64, BATCH), 512>>>(octx, tah, tal);

    // 6) MLP GEMM with fused combine epilogue
    ga.a[0] = {tah, tal, wh + OFF_NLW, nl_b, oself, cmh, cml, ratio,
               IDIM, IDIM, 2, 2, 0};
    gemm_u<<<256, 512, GEMM_SMEM>>>(ga, 1);

    // 7) final projection
    ga.a[0] = {cmh, cml, wh + OFF_WOUT, b_out, out, nullptr, nullptr, nullptr,
               IDIM, IDIM, 0, 0, 0};
    gemm_u<<<256, 512, GEMM_SMEM>>>(ga, 1);
}

// round 16
// speedup vs baseline: 1.5550x; 1.5550x over previous
#include <cuda_runtime.h>
#include <cuda_fp16.h>
#include <math.h>
#include <stdint.h>

#define BATCH 8
#define NTOK  1024
#define DMODEL 512
#define HEADS 8
#define DHEAD 64
#define CHh 6
#define CDd 64
#define IDIM 512
#define TOKENS (BATCH*NTOK)   // 8192
#define CKDIM (CHh*CDd)       // 384

typedef __half f16;

// ---------------- weight split offsets (elements) ------------------------------
#define OFF_WQKV 0
#define OFF_CKW0 786432
#define OFF_CKW1 983040
#define OFF_CKW2 1245184
#define OFF_CVW0 1507328
#define OFF_CVW1 1703936
#define OFF_CVW2 1966080
#define OFF_NLW  2228224
#define OFF_WOUT 2490368
#define W_TOTAL  2752512
#define X_ELEMS  (TOKENS * DMODEL)
#define ALL_SPLIT (W_TOTAL + X_ELEMS)

// ---------------- scratch ----------------------------------------------------
__device__ f16 g_wh[W_TOTAL];                 // weights: hi only
__device__ f16 g_xh[X_ELEMS], g_xl[X_ELEMS];
__device__ f16 g_qkvh[TOKENS * 3 * IDIM];     // qkv: hi only
__device__ f16 g_ckxh[TOKENS * CKDIM],    g_ckxl[TOKENS * CKDIM];
__device__ f16 g_cvxh[TOKENS * CKDIM],    g_cvxl[TOKENS * CKDIM];
__device__ f16 g_tah [TOKENS * IDIM],     g_tal [TOKENS * IDIM];
__device__ f16 g_tbh [TOKENS * IDIM],     g_tbl [TOKENS * IDIM];
__device__ f16 g_uah [TOKENS * IDIM],     g_ual [TOKENS * IDIM];
__device__ f16 g_ubh [TOKENS * IDIM],     g_ubl [TOKENS * IDIM];
__device__ f16 g_ckhh[TOKENS * IDIM];         // K ctx: hi only
__device__ f16 g_cvhh[TOKENS * IDIM];         // V ctx: hi only
__device__ f16 g_cmh [TOKENS * IDIM],     g_cml [TOKENS * IDIM];
__device__ float g_oself[TOKENS * IDIM];
__device__ float g_octx [TOKENS * IDIM];

// ---------------- helpers ----------------------------------------------------
__device__ __forceinline__ void mma_f16(float c[4],
    uint32_t a0, uint32_t a1, uint32_t a2, uint32_t a3,
    uint32_t b0, uint32_t b1)
{
    asm volatile(
        "mma.sync.aligned.m16n8k16.row.col.f32.f16.f16.f32 "
        "{%0,%1,%2,%3}, {%4,%5,%6,%7}, {%8,%9}, {%0,%1,%2,%3};\n"
        : "+f"(c[0]), "+f"(c[1]), "+f"(c[2]), "+f"(c[3])
        : "r"(a0), "r"(a1), "r"(a2), "r"(a3), "r"(b0), "r"(b1));
}
__device__ __forceinline__ void ldsm4(uint32_t& r0, uint32_t& r1, uint32_t& r2, uint32_t& r3,
                                      const void* p)
{
    uint32_t a = (uint32_t)__cvta_generic_to_shared(p);
    asm volatile("ldmatrix.sync.aligned.m8n8.x4.shared.b16 {%0,%1,%2,%3}, [%4];"
        : "=r"(r0), "=r"(r1), "=r"(r2), "=r"(r3) : "r"(a));
}
__device__ __forceinline__ void ldsm4t(uint32_t& r0, uint32_t& r1, uint32_t& r2, uint32_t& r3,
                                       const void* p)
{
    uint32_t a = (uint32_t)__cvta_generic_to_shared(p);
    asm volatile("ldmatrix.sync.aligned.m8n8.x4.trans.shared.b16 {%0,%1,%2,%3}, [%4];"
        : "=r"(r0), "=r"(r1), "=r"(r2), "=r"(r3) : "r"(a));
}
__device__ __forceinline__ void cp16(void* dst, const void* src) {
    uint32_t d = (uint32_t)__cvta_generic_to_shared(dst);
    asm volatile("cp.async.cg.shared.global [%0], [%1], 16;" :: "r"(d), "l"(src));
}
__device__ __forceinline__ uint32_t packh(float x, float y) {
    __half2 t = __floats2half2_rn(x, y);
    return *(uint32_t*)&t;
}
__device__ __forceinline__ void hilo(float x, float& h, float& l) {
    f16 hb = __float2half_rn(x);
    h = __half2float(hb);
    l = x - h;
}

// ---------------- pre-split (weights hi-only + x hi/lo) ------------------------
struct WSrcs { const float* p[10]; };

__global__ __launch_bounds__(256) void split_all(WSrcs w)
{
    const int offs[11] = {OFF_WQKV, OFF_CKW0, OFF_CKW1, OFF_CKW2, OFF_CVW0,
                          OFF_CVW1, OFF_CVW2, OFF_NLW, OFF_WOUT, W_TOTAL, ALL_SPLIT};
    int idx = (blockIdx.x * 256 + threadIdx.x) * 4;
    if (idx >= ALL_SPLIT) return;
    int seg = 0;
    while (idx >= offs[seg + 1]) seg++;
    float4 v = *(const float4*)(w.p[seg] + (idx - offs[seg]));
    float h0,l0,h1,l1,h2,l2,h3,l3;
    hilo(v.x,h0,l0); hilo(v.y,h1,l1); hilo(v.z,h2,l2); hilo(v.w,h3,l3);
    if (seg < 9) {
        *(uint32_t*)&g_wh[idx]     = packh(h0,h1);
        *(uint32_t*)&g_wh[idx + 2] = packh(h2,h3);
    } else {
        int di = idx - W_TOTAL;
        *(uint32_t*)&g_xh[di]     = packh(h0,h1);
        *(uint32_t*)&g_xh[di + 2] = packh(h2,h3);
        *(uint32_t*)&g_xl[di]     = packh(l0,l1);
        *(uint32_t*)&g_xl[di + 2] = packh(l2,l3);
    }
}

// ---------------- fp16 2-product GEMM, BK=64, 3-stage cp.async -----------------
// C = act((Ah+Al) @ Bh^T + bias). Tile 128x128, BK=64, 512 threads, 16 warps.
// Per-z runtime config: {N, K, act, aout}. aout: 0 fp32; 1 split; 2 fused
// combine (Ch/Cl = split(Cf - C*ratio)); 3 hi-only.
// qkvmode: z in {0,1,2} are tile-columns of config 0 (bx = z*4 + blockIdx.x);
// z=3 -> config 1, z=4 -> config 2. Otherwise: config = a[z], bx = blockIdx.x.
#define SLD 72
#define AST (128 * SLD)
#define STAGE_E (3 * AST)              // Ah|Al|Bh
#define GEMM_SMEM (3 * STAGE_E * 2)    // 165888 bytes

struct GArg {
    const f16 *Ah, *Al, *Bh;
    const float* bias;
    float* Cf;
    f16 *Ch, *Cl;
    const float* ratio;
    int N, K, act, aout;
};
struct GArg3 { GArg a[3]; };

__global__ __launch_bounds__(512) void gemm_u(GArg3 args, int qkvmode)
{
    extern __shared__ __align__(16) f16 smg[];
    int zc, bx;
    if (qkvmode) {
        if (blockIdx.z <= 2) { zc = 0; bx = blockIdx.z * 4 + blockIdx.x; }
        else                 { zc = blockIdx.z - 2; bx = blockIdx.x; }
    } else {
        zc = blockIdx.z; bx = blockIdx.x;
    }
    const GArg g = args.a[zc];
    const int N = g.N, K = g.K;
    const int by = blockIdx.y;
    const int tid = threadIdx.x, lane = tid & 31, warp = tid >> 5;
    const int lr = lane >> 2, lc = lane & 3;
    const int wm = warp >> 2, wn = warp & 3;

    const f16* AhB = g.Ah + (size_t)by * 128 * K;
    const f16* AlB = g.Al + (size_t)by * 128 * K;
    const f16* BhB = g.Bh + (size_t)bx * 128 * K;

    int lrow[2], lcg[2];
#pragma unroll
    for (int i = 0; i < 2; i++) {
        int f = tid + i * 512;
        lrow[i] = f >> 3;
        lcg[i] = (f & 7) * 8;
    }
    const int a_r = wm * 32 + (lane & 15);
    const int a_c0 = (lane >> 4) * 8;
    const int b_r = wn * 32 + (lane & 7) + ((lane & 16) ? 8 : 0);
    const int b_c0 = (lane & 8) ? 8 : 0;

    float acc[2][4][4];
#pragma unroll
    for (int i = 0; i < 2; i++)
#pragma unroll
        for (int j = 0; j < 4; j++)
#pragma unroll
            for (int r = 0; r < 4; r++) acc[i][j][r] = 0.0f;

    const int ktiles = K / 64;

    auto issue = [&](int kt, int buf) {
        f16* s = smg + buf * STAGE_E;
        int kg = kt * 64;
#pragma unroll
        for (int i = 0; i < 2; i++) {
            size_t go = (size_t)lrow[i] * K + kg + lcg[i];
            int so = lrow[i] * SLD + lcg[i];
            cp16(s + so,            AhB + go);
            cp16(s + AST + so,      AlB + go);
            cp16(s + 2 * AST + so,  BhB + go);
        }
        asm volatile("cp.async.commit_group;");
    };
    issue(0, 0);
    if (ktiles > 1) issue(1, 1);

    for (int kt = 0; kt < ktiles; kt++) {
        if (kt < ktiles - 1) asm volatile("cp.async.wait_group 1;");
        else                 asm volatile("cp.async.wait_group 0;");
        __syncthreads();
        if (kt + 2 < ktiles) issue(kt + 2, (kt + 2) % 3);

        const f16* s = smg + (kt % 3) * STAGE_E;
        const f16* AhS = s;
        const f16* AlS = s + AST;
        const f16* BhS = s + 2 * AST;
#pragma unroll
        for (int ks = 0; ks < 64; ks += 16) {
            uint32_t ah[2][4], al_[2][4], bh[4][2];
#pragma unroll
            for (int i = 0; i < 2; i++) {
                ldsm4(ah[i][0], ah[i][1], ah[i][2], ah[i][3],
                      AhS + (a_r + i * 16) * SLD + a_c0 + ks);
                ldsm4(al_[i][0], al_[i][1], al_[i][2], al_[i][3],
                      AlS + (a_r + i * 16) * SLD + a_c0 + ks);
            }
#pragma unroll
            for (int jp = 0; jp < 2; jp++) {
                ldsm4(bh[2*jp][0], bh[2*jp][1], bh[2*jp+1][0], bh[2*jp+1][1],
                      BhS + (b_r + jp * 16) * SLD + b_c0 + ks);
            }
#pragma unroll
            for (int i = 0; i < 2; i++)
#pragma unroll
                for (int j = 0; j < 4; j++)
                    mma_f16(acc[i][j], ah[i][0],ah[i][1],ah[i][2],ah[i][3], bh[j][0],bh[j][1]);
#pragma unroll
            for (int i = 0; i < 2; i++)
#pragma unroll
                for (int j = 0; j < 4; j++)
                    mma_f16(acc[i][j], al_[i][0],al_[i][1],al_[i][2],al_[i][3], bh[j][0],bh[j][1]);
        }
    }

    // epilogue (runtime act/aout)
#pragma unroll
    for (int i = 0; i < 2; i++) {
        int row0 = by * 128 + wm * 32 + i * 16 + lr;
#pragma unroll
        for (int j = 0; j < 4; j++) {
            int col = bx * 128 + wn * 32 + j * 8 + 2 * lc;
            float b0 = g.bias ? g.bias[col]     : 0.0f;
            float b1 = g.bias ? g.bias[col + 1] : 0.0f;
            float v[4];
            v[0] = acc[i][j][0] + b0; v[1] = acc[i][j][1] + b1;
            v[2] = acc[i][j][2] + b0; v[3] = acc[i][j][3] + b1;
#pragma unroll
            for (int r = 0; r < 4; r++) {
                float xx = v[r];
                if (g.act == 1) xx = xx > 0.0f ? xx : 0.2f * xx;
                else if (g.act == 2) xx = 0.5f * xx * (1.0f + erff(xx * 0.70710678118654752f));
                v[r] = xx;
            }
            if (g.aout == 0) {
                *(float2*)(g.Cf + (size_t)row0 * N + col)       = make_float2(v[0], v[1]);
                *(float2*)(g.Cf + (size_t)(row0 + 8) * N + col) = make_float2(v[2], v[3]);
            } else if (g.aout == 1) {
                float h0,l0,h1,l1;
                hilo(v[0],h0,l0); hilo(v[1],h1,l1);
                *(uint32_t*)&g.Ch[(size_t)row0 * N + col] = packh(h0,h1);
                *(uint32_t*)&g.Cl[(size_t)row0 * N + col] = packh(l0,l1);
                hilo(v[2],h0,l0); hilo(v[3],h1,l1);
                *(uint32_t*)&g.Ch[(size_t)(row0 + 8) * N + col] = packh(h0,h1);
                *(uint32_t*)&g.Cl[(size_t)(row0 + 8) * N + col] = packh(l0,l1);
            } else if (g.aout == 2) {
                float2 s0 = *(const float2*)(g.Cf + (size_t)row0 * N + col);
                float2 s1 = *(const float2*)(g.Cf + (size_t)(row0 + 8) * N + col);
                float2 rr = *(const float2*)(g.ratio + col);
                float c0 = s0.x - v[0] * rr.x, c1 = s0.y - v[1] * rr.y;
                float c2 = s1.x - v[2] * rr.x, c3 = s1.y - v[3] * rr.y;
                float h0,l0,h1,l1;
                hilo(c0,h0,l0); hilo(c1,h1,l1);
                *(uint32_t*)&g.Ch[(size_t)row0 * N + col] = packh(h0,h1);
                *(uint32_t*)&g.Cl[(size_t)row0 * N + col] = packh(l0,l1);
                hilo(c2,h0,l0); hilo(c3,h1,l1);
                *(uint32_t*)&g.Ch[(size_t)(row0 + 8) * N + col] = packh(h0,h1);
                *(uint32_t*)&g.Cl[(size_t)(row0 + 8) * N + col] = packh(l0,l1);
            } else {  // aout == 3: hi only
                *(uint32_t*)&g.Ch[(size_t)row0 * N + col]       = packh(v[0], v[1]);
                *(uint32_t*)&g.Ch[(size_t)(row0 + 8) * N + col] = packh(v[2], v[3]);
            }
        }
    }
}

// ---------------- fp16 fixed-base flash attention (static smem, high occupancy)
#define KLD 72

struct AArg {
    const f16 *Kh, *Vh;
    float* O;
    int ldkv;
};
struct AArg2 { AArg a[2]; };

__global__ __launch_bounds__(256) void attn_mma(
    const f16* __restrict__ Qh, AArg2 args, int ldq)
{
    __shared__ f16 Kh[64][KLD];
    __shared__ f16 Vh[64][KLD];
    const int b = blockIdx.z & 7, br = blockIdx.z >> 3;
    const int h = blockIdx.y, qt = blockIdx.x;
    const AArg ar = args.a[br];
    const int ldkv = ar.ldkv;
    const int tid = threadIdx.x;
    const int lane = tid & 31, warp = tid >> 5;
    const int lr = lane >> 2, lc = lane & 3;

    const f16* QhB = Qh + ((size_t)b * NTOK + qt * 128 + warp * 16) * ldq + h * 64;
    const f16* KhB = ar.Kh + ((size_t)b * NTOK) * ldkv + h * 64;
    const f16* VhB = ar.Vh + ((size_t)b * NTOK) * ldkv + h * 64;

    uint32_t qh[4][4];
#pragma unroll
    for (int kk = 0; kk < 4; kk++) {
        qh[kk][0] = *(const uint32_t*)&QhB[(size_t)lr * ldq + kk*16 + 2*lc];
        qh[kk][1] = *(const uint32_t*)&QhB[(size_t)(lr+8) * ldq + kk*16 + 2*lc];
        qh[kk][2] = *(const uint32_t*)&QhB[(size_t)lr * ldq + kk*16 + 8 + 2*lc];
        qh[kk][3] = *(const uint32_t*)&QhB[(size_t)(lr+8) * ldq + kk*16 + 8 + 2*lc];
    }

    int krow[2], kcg[2];
#pragma unroll
    for (int i = 0; i < 2; i++) {
        int f = tid + i * 256;
        krow[i] = f >> 3;
        kcg[i] = (f & 7) * 8;
    }
    const int k_r = (lane & 7) + ((lane & 16) ? 8 : 0);
    const int k_c = (lane & 8) ? 8 : 0;
    const int v_r = (lane & 7) + ((lane & 8) ? 8 : 0);
    const int v_c = (lane & 16) ? 8 : 0;

    float l0p = 0.0f, l1p = 0.0f;
    float o[8][4];
#pragma unroll
    for (int j = 0; j < 8; j++)
#pragma unroll
        for (int r = 0; r < 4; r++) o[j][r] = 0.0f;

    uint4 pkh[2], pvh[2];
#pragma unroll
    for (int i = 0; i < 2; i++) {
        size_t off = (size_t)krow[i] * ldkv + kcg[i];
        pkh[i] = *(const uint4*)(KhB + off);
        pvh[i] = *(const uint4*)(VhB + off);
    }

    for (int kt = 0; kt < NTOK / 64; kt++) {
        __syncthreads();
#pragma unroll
        for (int i = 0; i < 2; i++) {
            *(uint4*)&Kh[krow[i]][kcg[i]] = pkh[i];
            *(uint4*)&Vh[krow[i]][kcg[i]] = pvh[i];
        }
        __syncthreads();

        if (kt + 1 < NTOK / 64) {
            const f16* Kn = KhB + (size_t)(kt + 1) * 64 * ldkv;
            const f16* Vn = VhB + (size_t)(kt + 1) * 64 * ldkv;
#pragma unroll
            for (int i = 0; i < 2; i++) {
                size_t off = (size_t)krow[i] * ldkv + kcg[i];
                pkh[i] = *(const uint4*)(Kn + off);
                pvh[i] = *(const uint4*)(Vn + off);
            }
        }

        // S = Qh Kh^T
        float s[8][4];
#pragma unroll
        for (int j = 0; j < 8; j++)
#pragma unroll
            for (int r = 0; r < 4; r++) s[j][r] = 0.0f;
#pragma unroll
        for (int kk = 0; kk < 4; kk++) {
#pragma unroll
            for (int jp = 0; jp < 4; jp++) {
                uint32_t kb0,kb1,kb2,kb3;
                ldsm4(kb0,kb1,kb2,kb3, &Kh[jp*16 + k_r][kk*16 + k_c]);
                mma_f16(s[2*jp],   qh[kk][0],qh[kk][1],qh[kk][2],qh[kk][3], kb0, kb1);
                mma_f16(s[2*jp+1], qh[kk][0],qh[kk][1],qh[kk][2],qh[kk][3], kb2, kb3);
            }
        }

        // P = exp(s * scale); accumulate partial row sums
#pragma unroll
        for (int j = 0; j < 8; j++) {
            s[j][0] = __expf(s[j][0] * 0.125f);
            s[j][1] = __expf(s[j][1] * 0.125f);
            s[j][2] = __expf(s[j][2] * 0.125f);
            s[j][3] = __expf(s[j][3] * 0.125f);
            l0p += s[j][0] + s[j][1];
            l1p += s[j][2] + s[j][3];
        }

        // O += P V
#pragma unroll
        for (int kk = 0; kk < 4; kk++) {
            uint32_t pah0 = packh(s[2*kk][0],   s[2*kk][1]);
            uint32_t pah1 = packh(s[2*kk][2],   s[2*kk][3]);
            uint32_t pah2 = packh(s[2*kk+1][0], s[2*kk+1][1]);
            uint32_t pah3 = packh(s[2*kk+1][2], s[2*kk+1][3]);
#pragma unroll
            for (int jp = 0; jp < 4; jp++) {
                uint32_t vb0,vb1,vb2,vb3;
                ldsm4t(vb0,vb1,vb2,vb3, &Vh[kk*16 + v_r][jp*16 + v_c]);
                mma_f16(o[2*jp],   pah0,pah1,pah2,pah3, vb0, vb1);
                mma_f16(o[2*jp+1], pah0,pah1,pah2,pah3, vb2, vb3);
            }
        }
    }

    l0p += __shfl_xor_sync(0xffffffffu, l0p, 1);
    l0p += __shfl_xor_sync(0xffffffffu, l0p, 2);
    l1p += __shfl_xor_sync(0xffffffffu, l1p, 1);
    l1p += __shfl_xor_sync(0xffffffffu, l1p, 2);
    float inv0 = 1.0f / l0p, inv1 = 1.0f / l1p;

    float* Op = ar.O + ((size_t)b * NTOK + qt * 128 + warp * 16) * IDIM + h * 64;
#pragma unroll
    for (int j = 0; j < 8; j++) {
        int col = j * 8 + 2 * lc;
        *(float2*)(Op + (size_t)lr * IDIM + col)       = make_float2(o[j][0]*inv0, o[j][1]*inv0);
        *(float2*)(Op + (size_t)(lr + 8) * IDIM + col) = make_float2(o[j][2]*inv1, o[j][3]*inv1);
    }
}

// ---------------- column L2-norm (ck/cv batched, 512 threads) -------------------
__global__ __launch_bounds__(512) void colnorm_ck2(
    const float* __restrict__ s0, const float* __restrict__ s1)
{
    const int hh = blockIdx.x, b = blockIdx.y, z = blockIdx.z;
    const float* src = z ? s1 : s0;
    f16* dh = z ? g_cvxh : g_ckxh;
    f16* dl = z ? g_cvxl : g_ckxl;
    __shared__ float red[512];
    __shared__ float inv[64];
    const int tid = threadIdx.x;
    const int d = tid & 63;
    const int ng = tid >> 6;   // 0..7
    const float* s = src + (((size_t)b * CHh + hh) * NTOK) * CDd;
    float acc = 0.0f;
    for (int n = ng; n < NTOK; n += 8) {
        float v = s[(size_t)n * CDd + d];
        acc += v * v;
    }
    red[tid] = acc;
    __syncthreads();
    if (tid < 64) {
        float t = 0.0f;
#pragma unroll
        for (int i = 0; i < 8; i++) t += red[tid + i * 64];
        inv[tid] = 1.0f / fmaxf(sqrtf(t), 1e-12f);
    }
    __syncthreads();
    float iv = inv[d];
    f16* ph = dh + (size_t)b * NTOK * CKDIM + hh * CDd;
    f16* pl = dl + (size_t)b * NTOK * CKDIM + hh * CDd;
    for (int n = ng; n < NTOK; n += 8) {
        float v = s[(size_t)n * CDd + d] * iv;
        float h, l;
        hilo(v, h, l);
        ph[(size_t)n * CKDIM + d] = __float2half_rn(h);
        pl[(size_t)n * CKDIM + d] = __float2half_rn(l);
    }
}

__global__ __launch_bounds__(512) void colnorm_tok_kernel(
    const float* __restrict__ src, f16* __restrict__ dh, f16* __restrict__ dl)
{
    const int hh = blockIdx.x, b = blockIdx.y;
    __shared__ float red[512];
    __shared__ float inv[64];
    const int tid = threadIdx.x;
    const int d = tid & 63;
    const int ng = tid >> 6;   // 0..7
    const float* s = src + (size_t)b * NTOK * IDIM + hh * 64;
    float acc = 0.0f;
    for (int n = ng; n < NTOK; n += 8) {
        float v = s[(size_t)n * IDIM + d];
        acc += v * v;
    }
    red[tid] = acc;
    __syncthreads();
    if (tid < 64) {
        float t = 0.0f;
#pragma unroll
        for (int i = 0; i < 8; i++) t += red[tid + i * 64];
        inv[tid] = 1.0f / fmaxf(sqrtf(t), 1e-12f);
    }
    __syncthreads();
    float iv = inv[d];
    f16* ph = dh + (size_t)b * NTOK * IDIM + hh * 64;
    f16* pl = dl + (size_t)b * NTOK * IDIM + hh * 64;
    for (int n = ng; n < NTOK; n += 8) {
        float v = s[(size_t)n * IDIM + d] * iv;
        float h, l;
        hilo(v, h, l);
        ph[(size_t)n * IDIM + d] = __float2half_rn(h);
        pl[(size_t)n * IDIM + d] = __float2half_rn(l);
    }
}

// ---------------- launch -------------------------------------------------------
extern "C" void kernel_launch(void* const* d_in, const int* in_sizes, int n_in,
                              void* d_out, int out_size)
{
    const float* x      = (const float*)d_in[0];
    const float* ck     = (const float*)d_in[1];
    const float* cv     = (const float*)d_in[2];
    const float* b_out  = (const float*)d_in[5];
    const float* ckb0   = (const float*)d_in[7];
    const float* ckb1   = (const float*)d_in[9];
    const float* ckb2   = (const float*)d_in[11];
    const float* cvb0   = (const float*)d_in[13];
    const float* cvb1   = (const float*)d_in[15];
    const float* cvb2   = (const float*)d_in[17];
    const float* nl_b   = (const float*)d_in[19];
    const float* ratio  = (const float*)d_in[20];
    float* out = (float*)d_out;

    f16 *wh, *xh, *xl, *qkvh, *ckxh, *ckxl, *cvxh, *cvxl;
    f16 *tah, *tal, *tbh, *tbl, *uah, *ual, *ubh, *ubl;
    f16 *ckhh, *cvhh, *cmh, *cml;
    float *oself, *octx;
    cudaGetSymbolAddress((void**)&wh,   g_wh);
    cudaGetSymbolAddress((void**)&xh,   g_xh);
    cudaGetSymbolAddress((void**)&xl,   g_xl);
    cudaGetSymbolAddress((void**)&qkvh, g_qkvh);
    cudaGetSymbolAddress((void**)&ckxh, g_ckxh);
    cudaGetSymbolAddress((void**)&ckxl, g_ckxl);
    cudaGetSymbolAddress((void**)&cvxh, g_cvxh);
    cudaGetSymbolAddress((void**)&cvxl, g_cvxl);
    cudaGetSymbolAddress((void**)&tah,  g_tah);
    cudaGetSymbolAddress((void**)&tal,  g_tal);
    cudaGetSymbolAddress((void**)&tbh,  g_tbh);
    cudaGetSymbolAddress((void**)&tbl,  g_tbl);
    cudaGetSymbolAddress((void**)&uah,  g_uah);
    cudaGetSymbolAddress((void**)&ual,  g_ual);
    cudaGetSymbolAddress((void**)&ubh,  g_ubh);
    cudaGetSymbolAddress((void**)&ubl,  g_ubl);
    cudaGetSymbolAddress((void**)&ckhh, g_ckhh);
    cudaGetSymbolAddress((void**)&cvhh, g_cvhh);
    cudaGetSymbolAddress((void**)&cmh,  g_cmh);
    cudaGetSymbolAddress((void**)&cml,  g_cml);
    cudaGetSymbolAddress((void**)&oself,g_oself);
    cudaGetSymbolAddress((void**)&octx, g_octx);

    cudaFuncSetAttribute(gemm_u, cudaFuncAttributeMaxDynamicSharedMemorySize, GEMM_SMEM);

    // 0) pre-split weights (hi) + x (hi/lo)
    WSrcs ws;
    ws.p[0] = (const float*)d_in[3];  // w_qkv
    ws.p[1] = (const float*)d_in[6];  // ckw0
    ws.p[2] = (const float*)d_in[8];  // ckw1
    ws.p[3] = (const float*)d_in[10]; // ckw2
    ws.p[4] = (const float*)d_in[12]; // cvw0
    ws.p[5] = (const float*)d_in[14]; // cvw1
    ws.p[6] = (const float*)d_in[16]; // cvw2
    ws.p[7] = (const float*)d_in[18]; // nl_w
    ws.p[8] = (const float*)d_in[4];  // w_out
    ws.p[9] = x;
    split_all<<<(ALL_SPLIT / 4 + 255) / 256, 256>>>(ws);

    // 1) colnorm ck + cv (batched)
    colnorm_ck2<<<dim3(CHh, BATCH, 2), 512>>>(ck, cv);

    GArg3 ga;

    // 2) merged: qkv GEMM (z=0..2, 12 tile-cols) + L0 ck (z=3) + L0 cv (z=4).
    //    grid (4, 64, 5) = 1280 blocks, no dead blocks.
    ga.a[0] = {xh,   xl,   wh + OFF_WQKV, nullptr, nullptr, qkvh, nullptr, nullptr,
               3 * IDIM, DMODEL, 0, 3};
    ga.a[1] = {ckxh, ckxl, wh + OFF_CKW0, ckb0,    nullptr, tah,  tal,  nullptr,
               IDIM, CKDIM, 1, 1};
    ga.a[2] = {cvxh, cvxl, wh + OFF_CVW0, cvb0,    nullptr, uah,  ual,  nullptr,
               IDIM, CKDIM, 1, 1};
    gemm_u<<<dim3(4, TOKENS / 128, 5), 512, GEMM_SMEM>>>(ga, 1);

    // 3) vectorizer L1 (ck/cv batched)
    ga.a[0] = {tah, tal, wh + OFF_CKW1, ckb1, nullptr, tbh, tbl, nullptr,
               IDIM, IDIM, 1, 1};
    ga.a[1] = {uah, ual, wh + OFF_CVW1, cvb1, nullptr, ubh, ubl, nullptr,
               IDIM, IDIM, 1, 1};
    gemm_u<<<dim3(IDIM / 128, TOKENS / 128, 2), 512, GEMM_SMEM>>>(ga, 0);

    // 4) vectorizer L2 (ck/cv batched, hi-only out)
    ga.a[0] = {tbh, tbl, wh + OFF_CKW2, ckb2, nullptr, ckhh, nullptr, nullptr,
               IDIM, IDIM, 1, 3};
    ga.a[1] = {ubh, ubl, wh + OFF_CVW2, cvb2, nullptr, cvhh, nullptr, nullptr,
               IDIM, IDIM, 1, 3};
    gemm_u<<<dim3(IDIM / 128, TOKENS / 128, 2), 512, GEMM_SMEM>>>(ga, 0);

    // 5) both attention branches in one launch
    AArg2 aa;
    aa.a[0] = {qkvh + IDIM, qkvh + 2 * IDIM, oself, 3 * IDIM};
    aa.a[1] = {ckhh, cvhh, octx, IDIM};
    attn_mma<<<dim3(NTOK / 128, HEADS, 2 * BATCH), 256>>>(qkvh, aa, 3 * IDIM);

    // 6) MLP colnorm
    colnorm_tok_kernel<<<dim3(IDIM / 64, BATCH), 512>>>(octx, tah, tal);

    // 7) MLP GEMM with fused combine epilogue
    ga.a[0] = {tah, tal, wh + OFF_NLW, nl_b, oself, cmh, cml, ratio,
               IDIM, IDIM, 2, 2};
    gemm_u<<<dim3(IDIM / 128, TOKENS / 128, 1), 512, GEMM_SMEM>>>(ga, 0);

    // 8) final projection
    ga.a[0] = {cmh, cml, wh + OFF_WOUT, b_out, out, nullptr, nullptr, nullptr,
               IDIM, IDIM, 0, 0};
    gemm_u<<<dim3(IDIM / 128, TOKENS / 128, 1), 512, GEMM_SMEM>>>(ga, 0);
}